// round 11
// baseline (speedup 1.0000x reference)
#include <cuda_runtime.h>
#include <math.h>
#include <stdint.h>

// Problem: G=1, E=8, C=2048, H=1024, I=4096
#define EXPERTS 8
#define CDIM 2048
#define HDIM 1024
#define IDIM 4096

#define BM 128
#define BN 128
#define BK 32
#define NTHREADS 256
#define NSTAGES 3

// Rows are 32 floats (128B) = 8 16B slots; slot swizzle: j' = j ^ ((row&1)<<2)
#define A_STAGE_BYTES (BM * 128)                       // 16384
#define B_STAGE_BYTES (BN * 128)                       // 16384
#define STAGE_BYTES   (A_STAGE_BYTES + B_STAGE_BYTES)  // 32768
#define SMEM_TOTAL    (NSTAGES * STAGE_BYTES)          // 98304 -> 2 CTAs/SM

// K pre-permuted in groups of 16 (4x4 transpose): pos(k) = 4*(k&3) + (k>>2).
// float4 at slot q of a 16-group = [k=q, k=q+4, k=q+8, k=q+12]
//  -> one LDS.128 = fragments for TWO k8 MMA steps.

// Scratch (device globals; allocation APIs forbidden)
__device__ float g_hidden[(size_t)EXPERTS * CDIM * IDIM];  // 256 MB (K-permuted)
__device__ float g_xr[(size_t)EXPERTS * CDIM * HDIM];      // 64 MB  (K-permuted)
__device__ float g_wiT[(size_t)EXPERTS * HDIM * IDIM];     // 128 MB [E][I][H] (K-permuted)
__device__ float g_woT[(size_t)EXPERTS * HDIM * IDIM];     // 128 MB [E][H][I] (K-permuted)

__device__ __forceinline__ float tf32f(float x) {
    float y;
    asm("cvt.rna.tf32.f32 %0, %1;" : "=f"(y) : "f"(x));
    return y;
}
__device__ __forceinline__ float gelu_exact(float x) {
    return 0.5f * x * (1.0f + erff(x * 0.70710678118654752440f));
}
__device__ __forceinline__ uint32_t smem_u32(const void* p) {
    uint32_t a;
    asm("{ .reg .u64 t; cvta.to.shared.u64 t, %1; cvt.u32.u64 %0, t; }" : "=r"(a) : "l"(p));
    return a;
}
__device__ __forceinline__ void cp_async16(uint32_t dst, const void* src) {
    asm volatile("cp.async.cg.shared.global [%0], [%1], 16;"
                 :: "r"(dst), "l"(src) : "memory");
}
__device__ __forceinline__ void cp_commit() {
    asm volatile("cp.async.commit_group;" ::: "memory");
}
__device__ __forceinline__ void cp_wait1() {
    asm volatile("cp.async.wait_group 1;" ::: "memory");
}
#define MMA_TF32(accv, a0, a1, a2, a3, b0, b1)                                   \
    asm volatile(                                                                \
        "mma.sync.aligned.m16n8k8.row.col.f32.tf32.tf32.f32 "                    \
        "{%0,%1,%2,%3}, {%4,%5,%6,%7}, {%8,%9}, {%0,%1,%2,%3};\n"                \
        : "+f"((accv)[0]), "+f"((accv)[1]), "+f"((accv)[2]), "+f"((accv)[3])     \
        : "r"(__float_as_uint(a0)), "r"(__float_as_uint(a1)),                    \
          "r"(__float_as_uint(a2)), "r"(__float_as_uint(a3)),                    \
          "r"(__float_as_uint(b0)), "r"(__float_as_uint(b1)))

// ---------------- tf32 round + K-permute (16-groups, 4x4 transpose) ---------
__global__ void __launch_bounds__(256)
round_perm_tf32(const float* __restrict__ in, float* __restrict__ out, size_t n16)
{
    size_t j = (size_t)blockIdx.x * 256 + threadIdx.x;
    if (j >= n16) return;
    const float4* ip = reinterpret_cast<const float4*>(in + 16 * j);
    float4 f0 = ip[0], f1 = ip[1], f2 = ip[2], f3 = ip[3];
    float4* op = reinterpret_cast<float4*>(out + 16 * j);
    op[0] = make_float4(tf32f(f0.x), tf32f(f1.x), tf32f(f2.x), tf32f(f3.x));
    op[1] = make_float4(tf32f(f0.y), tf32f(f1.y), tf32f(f2.y), tf32f(f3.y));
    op[2] = make_float4(tf32f(f0.z), tf32f(f1.z), tf32f(f2.z), tf32f(f3.z));
    op[3] = make_float4(tf32f(f0.w), tf32f(f1.w), tf32f(f2.w), tf32f(f3.w));
}

// ---------------- transpose + tf32 round + 16-group K-permute on minor dim --
__global__ void __launch_bounds__(256)
transpose_cvt_perm(const float* __restrict__ in, float* __restrict__ out, int R, int C)
{
    __shared__ float tile[32][33];
    const int e = blockIdx.z;
    in  += (size_t)e * R * C;
    out += (size_t)e * R * C;
    const int c0 = blockIdx.x * 32;
    const int r0 = blockIdx.y * 32;
    const int tx = threadIdx.x;
    #pragma unroll
    for (int i = threadIdx.y; i < 32; i += 8)
        tile[i][tx] = in[(size_t)(r0 + i) * C + c0 + tx];
    __syncthreads();
    // position p holds source s = 4*(p&3) + (p>>2)  (4x4 transpose, self-inverse)
    const int p = tx & 15;
    const int src = (tx & ~15) | (4 * (p & 3) + (p >> 2));
    #pragma unroll
    for (int i = threadIdx.y; i < 32; i += 8)
        out[(size_t)(c0 + i) * R + r0 + tx] = tf32f(tile[src][i]);
}

// ---------------- pipelined tf32 mma.sync GEMM (16-perm K inputs) -----------
// D[M,N] = act(A[M,K] @ BT[N,K]^T) per expert (blockIdx.z).
template <bool GELU, int K, int N>
__global__ void __launch_bounds__(NTHREADS, 2)
gemm_tf32(const float* __restrict__ A, const float* __restrict__ BT,
          float* __restrict__ D)
{
    constexpr int M = CDIM;
    constexpr int nch = K / BK;

    extern __shared__ char smem[];
    const uint32_t sb = smem_u32(smem);

    const int e = blockIdx.z;
    A  += (size_t)e * M * K;
    BT += (size_t)e * N * K;
    D  += (size_t)e * M * N;

    const int tid  = threadIdx.x;
    const int lane = tid & 31;
    const int warp = tid >> 5;
    const int m0 = blockIdx.y * BM;
    const int n0 = blockIdx.x * BN;

    // 8 warps: 2 along M (64 rows), 4 along N (32 cols)
    const int wm = (warp & 1) * 64;
    const int wn = (warp >> 1) * 32;
    const int q  = lane & 3;
    const int r  = lane >> 2;

    // --- loop-invariant addressing ---
    // cp.async: thread covers rows r0g+32i, quad q4; slot swizzle by row parity
    const int r0g = tid >> 3;
    const int q4  = tid & 7;
    const int q4s = q4 ^ ((r0g & 1) << 2);
    const char* gA = reinterpret_cast<const char*>(A + (size_t)(m0 + r0g) * K) + q4 * 16;
    const char* gB = reinterpret_cast<const char*>(BT + (size_t)(n0 + r0g) * K) + q4 * 16;
    const uint32_t dstA0 = (uint32_t)(r0g * 128 + q4s * 16);
    const uint32_t dstB0 = dstA0 + A_STAGE_BYTES;

    // LDS.128 column byte offsets per 16-group g: ((4g+q)^((r&1)<<2))*16
    uint32_t colb[2];
    #pragma unroll
    for (int g = 0; g < 2; ++g)
        colb[g] = (uint32_t)((((g << 2) | q) ^ ((r & 1) << 2)) << 4);
    const uint32_t arow = (uint32_t)((wm + r) * 128);
    const uint32_t brow = (uint32_t)((wn + r) * 128) + A_STAGE_BYTES;

    float acc[4][4][4];
    #pragma unroll
    for (int i = 0; i < 4; i++)
        #pragma unroll
        for (int j = 0; j < 4; j++) {
            acc[i][j][0] = 0.f; acc[i][j][1] = 0.f;
            acc[i][j][2] = 0.f; acc[i][j][3] = 0.f;
        }

    // prologue: stages 0 and 1
    #pragma unroll
    for (int s = 0; s < 2; ++s) {
        const uint32_t ab = sb + (uint32_t)s * STAGE_BYTES + dstA0;
        const uint32_t bb = sb + (uint32_t)s * STAGE_BYTES + dstB0;
        #pragma unroll
        for (int i = 0; i < 4; ++i)
            cp_async16(ab + i * 4096, gA + (size_t)i * (32 * K * 4));
        #pragma unroll
        for (int i = 0; i < 4; ++i)
            cp_async16(bb + i * 4096, gB + (size_t)i * (32 * K * 4));
        cp_commit();
        gA += BK * 4; gB += BK * 4;
    }

    uint32_t soff_c = 0;                 // stage being consumed
    uint32_t soff_p = 2 * STAGE_BYTES;   // stage being produced

    #pragma unroll 1
    for (int t = 0; t < nch; ++t) {
        cp_wait1();
        __syncthreads();

        if (t + 2 < nch) {
            const uint32_t ab = sb + soff_p + dstA0;
            const uint32_t bb = sb + soff_p + dstB0;
            #pragma unroll
            for (int i = 0; i < 4; ++i)
                cp_async16(ab + i * 4096, gA + (size_t)i * (32 * K * 4));
            #pragma unroll
            for (int i = 0; i < 4; ++i)
                cp_async16(bb + i * 4096, gB + (size_t)i * (32 * K * 4));
            gA += BK * 4; gB += BK * 4;
            soff_p = (soff_p == 2 * STAGE_BYTES) ? 0u : soff_p + STAGE_BYTES;
        }
        cp_commit();   // empty group ok — keeps numbering aligned

        const char* Ab = smem + soff_c + arow;
        const char* Bb = smem + soff_c + brow;
        soff_c = (soff_c == 2 * STAGE_BYTES) ? 0u : soff_c + STAGE_BYTES;

        #pragma unroll
        for (int g = 0; g < 2; ++g) {    // 16-group = two k8 MMA steps
            const uint32_t cb = colb[g];

            float4 va[4][2];   // [mf][0]: rows m..m+7 ; [1]: rows m+8..m+15
            #pragma unroll
            for (int mf = 0; mf < 4; mf++) {
                va[mf][0] = *reinterpret_cast<const float4*>(Ab + mf * 2048 + cb);
                va[mf][1] = *reinterpret_cast<const float4*>(Ab + mf * 2048 + 1024 + cb);
            }
            float4 vb[4];
            #pragma unroll
            for (int nf = 0; nf < 4; nf++)
                vb[nf] = *reinterpret_cast<const float4*>(Bb + nf * 1024 + cb);

            #pragma unroll
            for (int mf = 0; mf < 4; mf++)
                #pragma unroll
                for (int nf = 0; nf < 4; nf++) {
                    // k8 step A (k = 16g + {q, q+4})
                    MMA_TF32(acc[mf][nf], va[mf][0].x, va[mf][1].x,
                             va[mf][0].y, va[mf][1].y, vb[nf].x, vb[nf].y);
                    // k8 step B (k = 16g + {q+8, q+12})
                    MMA_TF32(acc[mf][nf], va[mf][0].z, va[mf][1].z,
                             va[mf][0].w, va[mf][1].w, vb[nf].z, vb[nf].w);
                }
        }
    }

    // Epilogue
    #pragma unroll
    for (int mf = 0; mf < 4; mf++) {
        #pragma unroll
        for (int nf = 0; nf < 4; nf++) {
            const int row = m0 + wm + mf * 16 + r;
            const int nb  = n0 + wn + nf * 8;
            float v0 = acc[mf][nf][0];
            float v1 = acc[mf][nf][1];
            float v2 = acc[mf][nf][2];
            float v3 = acc[mf][nf][3];
            if (GELU) {
                // gelu + tf32-round, write 16-group K-PERMUTED along N for GEMM2
                v0 = tf32f(gelu_exact(v0)); v1 = tf32f(gelu_exact(v1));
                v2 = tf32f(gelu_exact(v2)); v3 = tf32f(gelu_exact(v3));
                const int g16 = nb & ~15;
                const int s0  = (nb & 15) | (2 * q);
                const int s1  = s0 + 1;
                const int p0  = 4 * (s0 & 3) + (s0 >> 2);
                const int p1  = 4 * (s1 & 3) + (s1 >> 2);
                D[(size_t)row * N + g16 + p0] = v0;
                D[(size_t)row * N + g16 + p1] = v1;
                D[(size_t)(row + 8) * N + g16 + p0] = v2;
                D[(size_t)(row + 8) * N + g16 + p1] = v3;
            } else {
                const int col = nb + 2 * q;
                *reinterpret_cast<float2*>(&D[(size_t)row * N + col]) = make_float2(v0, v1);
                *reinterpret_cast<float2*>(&D[(size_t)(row + 8) * N + col]) = make_float2(v2, v3);
            }
        }
    }
}

// ---------------- launch ----------------
extern "C" void kernel_launch(void* const* d_in, const int* in_sizes, int n_in,
                              void* d_out, int out_size) {
    (void)in_sizes; (void)n_in; (void)out_size;
    const float* x  = (const float*)d_in[0];  // [E][C][H]
    const float* wi = (const float*)d_in[1];  // [E][H][I]
    const float* wo = (const float*)d_in[2];  // [E][I][H]
    float* out = (float*)d_out;               // [E][C][H]

    float *hidden, *xr, *wiT, *woT;
    cudaGetSymbolAddress((void**)&hidden, g_hidden);
    cudaGetSymbolAddress((void**)&xr, g_xr);
    cudaGetSymbolAddress((void**)&wiT, g_wiT);
    cudaGetSymbolAddress((void**)&woT, g_woT);

    cudaFuncSetAttribute((const void*)gemm_tf32<true, HDIM, IDIM>,
                         cudaFuncAttributeMaxDynamicSharedMemorySize, SMEM_TOTAL);
    cudaFuncSetAttribute((const void*)gemm_tf32<false, IDIM, HDIM>,
                         cudaFuncAttributeMaxDynamicSharedMemorySize, SMEM_TOTAL);

    // Pre-round + 16-group K-permute x; pre-transpose + round + permute weights
    const size_t n16 = (size_t)EXPERTS * CDIM * HDIM / 16;
    round_perm_tf32<<<(unsigned)((n16 + 255) / 256), 256>>>(x, xr, n16);
    transpose_cvt_perm<<<dim3(IDIM / 32, HDIM / 32, EXPERTS), dim3(32, 8)>>>(wi, wiT, HDIM, IDIM);
    transpose_cvt_perm<<<dim3(HDIM / 32, IDIM / 32, EXPERTS), dim3(32, 8)>>>(wo, woT, IDIM, HDIM);

    // GEMM1 + GELU: hidden[C,I] = gelu(xr[C,H] @ wiT[I,H]^T)   (hidden K-permuted)
    gemm_tf32<true, HDIM, IDIM><<<dim3(IDIM / BN, CDIM / BM, EXPERTS), NTHREADS, SMEM_TOTAL>>>(
        xr, wiT, hidden);
    // GEMM2: out[C,H] = hidden[C,I] @ woT[H,I]^T
    gemm_tf32<false, IDIM, HDIM><<<dim3(HDIM / BN, CDIM / BM, EXPERTS), NTHREADS, SMEM_TOTAL>>>(
        hidden, woT, out);
}

// round 14
// speedup vs baseline: 1.9527x; 1.9527x over previous
#include <cuda_runtime.h>
#include <cuda_fp16.h>
#include <math.h>
#include <stdint.h>

// Problem: G=1, E=8, C=2048, H=1024, I=4096
#define EXPERTS 8
#define CDIM 2048
#define HDIM 1024
#define IDIM 4096

#define BM 128
#define BN 128
#define BK 64            // fp16 elements per chunk -> 128B rows
#define NTHREADS 256
#define NSTAGES 3

// Rows 128B; 8B pairs XOR-swizzled: pair' = pair ^ ((row&3)<<2)  (16 pairs/row)
#define A_STAGE_BYTES (BM * 128)                       // 16384
#define B_STAGE_BYTES (BN * 128)                       // 16384
#define STAGE_BYTES   (A_STAGE_BYTES + B_STAGE_BYTES)  // 32768
#define SMEM_TOTAL    (NSTAGES * STAGE_BYTES)          // 98304 -> 2 CTAs/SM

// K pre-permuted per 16-element group at 4B-unit level (unit = half2):
// source unit s (elems 2s,2s+1) stored at pos(s) = s<4 ? 2s : 2(s-4)+1.
// -> 8B pair q of a group = units (q, q+4): one LDS.64 = (a0,a2) / (b0,b1).

#define WSCALE 256.0f           // weight pre-scale (kills fp16 subnormal tail)
#define INV_WSCALE (1.0f / 256.0f)

// Scratch (device globals; allocation APIs forbidden)
__device__ __half g_hidden[(size_t)EXPERTS * CDIM * IDIM]; // 128 MB (K-permuted fp16)
__device__ __half g_xr[(size_t)EXPERTS * CDIM * HDIM];     // 32 MB  (K-permuted fp16)
__device__ __half g_wiT[(size_t)EXPERTS * HDIM * IDIM];    // 64 MB [E][I][H] (perm, x256)
__device__ __half g_woT[(size_t)EXPERTS * HDIM * IDIM];    // 64 MB [E][H][I] (perm, x256)

__device__ __forceinline__ float gelu_exact(float x) {
    return 0.5f * x * (1.0f + erff(x * 0.70710678118654752440f));
}
__device__ __forceinline__ uint32_t smem_u32(const void* p) {
    uint32_t a;
    asm("{ .reg .u64 t; cvta.to.shared.u64 t, %1; cvt.u32.u64 %0, t; }" : "=r"(a) : "l"(p));
    return a;
}
__device__ __forceinline__ void cp_async16(uint32_t dst, const void* src) {
    asm volatile("cp.async.cg.shared.global [%0], [%1], 16;"
                 :: "r"(dst), "l"(src) : "memory");
}
__device__ __forceinline__ void cp_commit() {
    asm volatile("cp.async.commit_group;" ::: "memory");
}
__device__ __forceinline__ void cp_wait1() {
    asm volatile("cp.async.wait_group 1;" ::: "memory");
}
// fp16 MMA: D(fp32) += A(f16) * B(f16); a0=(r,kq lo8) a1=(r+8) a2=(r,k hi8) a3=(r+8)
#define MMA_F16(accv, a0, a1, a2, a3, b0, b1)                                    \
    asm volatile(                                                                \
        "mma.sync.aligned.m16n8k16.row.col.f32.f16.f16.f32 "                     \
        "{%0,%1,%2,%3}, {%4,%5,%6,%7}, {%8,%9}, {%0,%1,%2,%3};\n"                \
        : "+f"((accv)[0]), "+f"((accv)[1]), "+f"((accv)[2]), "+f"((accv)[3])     \
        : "r"(a0), "r"(a1), "r"(a2), "r"(a3), "r"(b0), "r"(b1))

// ---------------- x: fp32 -> fp16, 16-group unit permute ----------------
__global__ void __launch_bounds__(256)
cvt_perm_h(const float* __restrict__ in, __half* __restrict__ out, size_t n16)
{
    size_t j = (size_t)blockIdx.x * 256 + threadIdx.x;
    if (j >= n16) return;
    const float4* ip = reinterpret_cast<const float4*>(in + 16 * j);
    float v[16];
    #pragma unroll
    for (int i = 0; i < 4; ++i) {
        float4 f = ip[i];
        v[4 * i] = f.x; v[4 * i + 1] = f.y; v[4 * i + 2] = f.z; v[4 * i + 3] = f.w;
    }
    __half2 u[8];
    #pragma unroll
    for (int s = 0; s < 8; ++s) {
        const int pos = (s < 4) ? 2 * s : 2 * (s - 4) + 1;
        u[pos] = __halves2half2(__float2half_rn(v[2 * s]), __float2half_rn(v[2 * s + 1]));
    }
    uint4* op = reinterpret_cast<uint4*>(out + 16 * j);
    const uint32_t* ub = reinterpret_cast<const uint32_t*>(u);
    op[0] = make_uint4(ub[0], ub[1], ub[2], ub[3]);
    op[1] = make_uint4(ub[4], ub[5], ub[6], ub[7]);
}

// ------- weights: transpose + fp32->fp16 (xWSCALE) + 16-group unit permute --
// out[e][c][r'] = half(in[e][r][c] * scale), minor dim permuted per 16-group.
__global__ void __launch_bounds__(256)
transpose_cvt_perm_h(const float* __restrict__ in, __half* __restrict__ out,
                     int R, int C)
{
    __shared__ float tile[32][33];
    const int e = blockIdx.z;
    in  += (size_t)e * R * C;
    out += (size_t)e * R * C;
    const int c0 = blockIdx.x * 32;
    const int r0 = blockIdx.y * 32;
    const int tx = threadIdx.x;
    #pragma unroll
    for (int i = threadIdx.y; i < 32; i += 8)
        tile[i][tx] = in[(size_t)(r0 + i) * C + c0 + tx];
    __syncthreads();
    // output elem position p in 16-group: unit pos up=p>>1; source unit:
    // up even -> up/2 ; up odd -> up/2 + 4 ; source elem = 2*su + (p&1)
    const int p  = tx & 15;
    const int up = p >> 1;
    const int su = (up & 1) ? ((up >> 1) + 4) : (up >> 1);
    const int src = (tx & ~15) | (2 * su + (p & 1));
    #pragma unroll
    for (int i = threadIdx.y; i < 32; i += 8)
        out[(size_t)(c0 + i) * R + r0 + tx] = __float2half_rn(tile[src][i] * WSCALE);
}

// ---------------- pipelined fp16 mma.sync GEMM (perm-K inputs) ---------------
// acc[M,N] = A[M,K] @ BT[N,K]^T per expert (blockIdx.z); B pre-scaled xWSCALE.
// GELU=true : D = __half*, writes half2 gelu(acc/WSCALE), N-permuted (feeds GEMM2)
// GELU=false: D = float*,  writes acc/WSCALE
template <bool GELU, int K, int N>
__global__ void __launch_bounds__(NTHREADS, 2)
gemm_f16(const __half* __restrict__ A, const __half* __restrict__ BT, void* Dv)
{
    constexpr int M = CDIM;
    constexpr int nch = K / BK;

    extern __shared__ char smem[];
    const uint32_t sb = smem_u32(smem);

    const int e = blockIdx.z;
    A  += (size_t)e * M * K;
    BT += (size_t)e * N * K;

    const int tid  = threadIdx.x;
    const int lane = tid & 31;
    const int warp = tid >> 5;
    const int m0 = blockIdx.y * BM;
    const int n0 = blockIdx.x * BN;

    // 8 warps: 2 along M (64 rows), 4 along N (32 cols)
    const int wm = (warp & 1) * 64;
    const int wn = (warp >> 1) * 32;
    const int q  = lane & 3;
    const int r  = lane >> 2;

    // cp.async: thread covers rows r0g+32i, 16B-quad q4; swizzle q4^((row&3)<<1)
    const int r0g = tid >> 3;
    const int q4  = tid & 7;
    const int q4s = q4 ^ ((r0g & 3) << 1);
    const char* gA = reinterpret_cast<const char*>(A + (size_t)(m0 + r0g) * K) + q4 * 16;
    const char* gB = reinterpret_cast<const char*>(BT + (size_t)(n0 + r0g) * K) + q4 * 16;
    const uint32_t dstA0 = (uint32_t)(r0g * 128 + q4s * 16);
    const uint32_t dstB0 = dstA0 + A_STAGE_BYTES;

    // LDS.64 pair offsets per k16 step kk: pair = kk*4+q, swizzled by r&3
    uint32_t pb[4];
    #pragma unroll
    for (int kk = 0; kk < 4; ++kk)
        pb[kk] = (uint32_t)((((kk << 2) | q) ^ ((r & 3) << 2)) << 3);
    const uint32_t arow = (uint32_t)((wm + r) * 128);
    const uint32_t brow = (uint32_t)((wn + r) * 128) + A_STAGE_BYTES;

    float acc[4][4][4];
    #pragma unroll
    for (int i = 0; i < 4; i++)
        #pragma unroll
        for (int j = 0; j < 4; j++) {
            acc[i][j][0] = 0.f; acc[i][j][1] = 0.f;
            acc[i][j][2] = 0.f; acc[i][j][3] = 0.f;
        }

    // prologue: stages 0 and 1
    #pragma unroll
    for (int s = 0; s < 2; ++s) {
        const uint32_t ab = sb + (uint32_t)s * STAGE_BYTES + dstA0;
        const uint32_t bb = sb + (uint32_t)s * STAGE_BYTES + dstB0;
        #pragma unroll
        for (int i = 0; i < 4; ++i)
            cp_async16(ab + i * 4096, gA + (size_t)i * (32 * K * 2));
        #pragma unroll
        for (int i = 0; i < 4; ++i)
            cp_async16(bb + i * 4096, gB + (size_t)i * (32 * K * 2));
        cp_commit();
        gA += BK * 2; gB += BK * 2;
    }

    uint32_t soff_c = 0;
    uint32_t soff_p = 2 * STAGE_BYTES;

    #pragma unroll 1
    for (int t = 0; t < nch; ++t) {
        cp_wait1();
        __syncthreads();

        if (t + 2 < nch) {
            const uint32_t ab = sb + soff_p + dstA0;
            const uint32_t bb = sb + soff_p + dstB0;
            #pragma unroll
            for (int i = 0; i < 4; ++i)
                cp_async16(ab + i * 4096, gA + (size_t)i * (32 * K * 2));
            #pragma unroll
            for (int i = 0; i < 4; ++i)
                cp_async16(bb + i * 4096, gB + (size_t)i * (32 * K * 2));
            gA += BK * 2; gB += BK * 2;
            soff_p = (soff_p == 2 * STAGE_BYTES) ? 0u : soff_p + STAGE_BYTES;
        }
        cp_commit();   // empty group ok — keeps numbering aligned

        const char* Ab = smem + soff_c + arow;
        const char* Bb = smem + soff_c + brow;
        soff_c = (soff_c == 2 * STAGE_BYTES) ? 0u : soff_c + STAGE_BYTES;

        #pragma unroll
        for (int kk = 0; kk < 4; ++kk) {      // 4 k16 steps = k64 chunk
            const char* Ak = Ab + pb[kk];
            const char* Bk = Bb + pb[kk];

            uint2 afl[4], afh[4], bfp[4];
            #pragma unroll
            for (int mf = 0; mf < 4; mf++) {
                afl[mf] = *reinterpret_cast<const uint2*>(Ak + mf * 2048);          // a0,a2
                afh[mf] = *reinterpret_cast<const uint2*>(Ak + mf * 2048 + 1024);   // a1,a3
            }
            #pragma unroll
            for (int nf = 0; nf < 4; nf++)
                bfp[nf] = *reinterpret_cast<const uint2*>(Bk + nf * 1024);          // b0,b1

            #pragma unroll
            for (int mf = 0; mf < 4; mf++)
                #pragma unroll
                for (int nf = 0; nf < 4; nf++)
                    MMA_F16(acc[mf][nf], afl[mf].x, afh[mf].x, afl[mf].y, afh[mf].y,
                            bfp[nf].x, bfp[nf].y);
        }
    }

    // Epilogue
    #pragma unroll
    for (int mf = 0; mf < 4; mf++) {
        #pragma unroll
        for (int nf = 0; nf < 4; nf++) {
            const int row = m0 + wm + mf * 16 + r;
            const int nb  = n0 + wn + nf * 8;
            float v0 = acc[mf][nf][0] * INV_WSCALE;
            float v1 = acc[mf][nf][1] * INV_WSCALE;
            float v2 = acc[mf][nf][2] * INV_WSCALE;
            float v3 = acc[mf][nf][3] * INV_WSCALE;
            if (GELU) {
                __half* Dh = reinterpret_cast<__half*>(Dv) + (size_t)e * M * N;
                v0 = gelu_exact(v0); v1 = gelu_exact(v1);
                v2 = gelu_exact(v2); v3 = gelu_exact(v3);
                // half2 (cols 2q,2q+1) stored at permuted unit position
                const int u   = (nb >> 1) + q;       // global unit index
                const int Gu  = u & ~7;
                const int s   = u & 7;
                const int pos = (s < 4) ? 2 * s : 2 * (s - 4) + 1;
                const size_t elem = 2 * (size_t)(Gu + pos);
                *reinterpret_cast<__half2*>(Dh + (size_t)row * N + elem) =
                    __halves2half2(__float2half_rn(v0), __float2half_rn(v1));
                *reinterpret_cast<__half2*>(Dh + (size_t)(row + 8) * N + elem) =
                    __halves2half2(__float2half_rn(v2), __float2half_rn(v3));
            } else {
                float* Df = reinterpret_cast<float*>(Dv) + (size_t)e * M * N;
                const int col = nb + 2 * q;
                *reinterpret_cast<float2*>(&Df[(size_t)row * N + col]) = make_float2(v0, v1);
                *reinterpret_cast<float2*>(&Df[(size_t)(row + 8) * N + col]) = make_float2(v2, v3);
            }
        }
    }
}

// ---------------- launch ----------------
extern "C" void kernel_launch(void* const* d_in, const int* in_sizes, int n_in,
                              void* d_out, int out_size) {
    (void)in_sizes; (void)n_in; (void)out_size;
    const float* x  = (const float*)d_in[0];  // [E][C][H]
    const float* wi = (const float*)d_in[1];  // [E][H][I]
    const float* wo = (const float*)d_in[2];  // [E][I][H]
    float* out = (float*)d_out;               // [E][C][H]

    __half *hidden, *xr, *wiT, *woT;
    cudaGetSymbolAddress((void**)&hidden, g_hidden);
    cudaGetSymbolAddress((void**)&xr, g_xr);
    cudaGetSymbolAddress((void**)&wiT, g_wiT);
    cudaGetSymbolAddress((void**)&woT, g_woT);

    cudaFuncSetAttribute((const void*)gemm_f16<true, HDIM, IDIM>,
                         cudaFuncAttributeMaxDynamicSharedMemorySize, SMEM_TOTAL);
    cudaFuncSetAttribute((const void*)gemm_f16<false, IDIM, HDIM>,
                         cudaFuncAttributeMaxDynamicSharedMemorySize, SMEM_TOTAL);

    // Pre-convert: x -> fp16 perm; weights -> transpose + fp16(xWSCALE) + perm
    const size_t n16 = (size_t)EXPERTS * CDIM * HDIM / 16;
    cvt_perm_h<<<(unsigned)((n16 + 255) / 256), 256>>>(x, xr, n16);
    transpose_cvt_perm_h<<<dim3(IDIM / 32, HDIM / 32, EXPERTS), dim3(32, 8)>>>(wi, wiT, HDIM, IDIM);
    transpose_cvt_perm_h<<<dim3(HDIM / 32, IDIM / 32, EXPERTS), dim3(32, 8)>>>(wo, woT, IDIM, HDIM);

    // GEMM1 + GELU: hidden = gelu(x @ wiT^T)  (hidden fp16, K-permuted)
    gemm_f16<true, HDIM, IDIM><<<dim3(IDIM / BN, CDIM / BM, EXPERTS), NTHREADS, SMEM_TOTAL>>>(
        xr, wiT, (void*)hidden);
    // GEMM2: out = hidden @ woT^T  (fp32 out)
    gemm_f16<false, IDIM, HDIM><<<dim3(HDIM / BN, CDIM / BM, EXPERTS), NTHREADS, SMEM_TOTAL>>>(
        hidden, woT, (void*)out);
}